// round 13
// baseline (speedup 1.0000x reference)
#include <cuda_runtime.h>

#define NB   2048
#define ND   128
#define TILE 32          // output tile edge (32x32), 64-thread blocks
#define KCH  32          // dims per pipeline stage
#define NCH  (ND / KCH)

// exponent constants, pre-scaled by log2(e) for ex2.approx
#define K_MIN  18.755035531556525f    //  13.0 * log2(e)
#define K_ABS  -9.3775177657782625f   //  -6.5 * log2(e)

// Scratch
__device__ float g_XT[ND * NB];
__device__ float g_ET[ND * NB];
__device__ float g_P[NB];     // K_ABS * sum over d%4!=3 of attn*x
__device__ float g_Q[NB];

__device__ __forceinline__ void cp16(unsigned smem_addr, const void* gptr) {
    asm volatile("cp.async.ca.shared.global [%0], [%1], 16;\n"
                 :: "r"(smem_addr), "l"(gptr));
}
__device__ __forceinline__ void cp_commit() {
    asm volatile("cp.async.commit_group;\n");
}
template<int N>
__device__ __forceinline__ void cp_wait() {
    asm volatile("cp.async.wait_group %0;\n" :: "n"(N));
}
__device__ __forceinline__ float ex2(float x) {
    float r; asm("ex2.approx.f32 %0, %1;" : "=f"(r) : "f"(x)); return r;
}

// ---------------------------------------------------------------------------
// Prep: transpose + attn-scale + partial rowsum (d%4 != 3), log2e-scaled.
// ---------------------------------------------------------------------------
__global__ __launch_bounds__(256) void prep2_kernel(
    const float* __restrict__ X, const float* __restrict__ E,
    const float* __restrict__ attn)
{
    __shared__ float a[ND];
    __shared__ float T[32][ND + 1];

    int bid = blockIdx.x;
    bool isE = bid >= 64;
    const float* src = isE ? E : X;
    float* dstT      = isE ? g_ET : g_XT;
    float* sums      = isE ? g_Q  : g_P;
    int rowbase = (bid & 63) * 32;

    int t = threadIdx.x;
    if (t < ND) a[t] = attn[t];
    __syncthreads();

    int r   = t >> 3;
    int seg = t & 7;
    const float4* srow = (const float4*)&src[(rowbase + r) * ND + seg * 16];
    float s = 0.0f;
    #pragma unroll
    for (int k = 0; k < 4; k++) {
        float4 v = srow[k];
        int d = seg * 16 + k * 4;
        v.x *= a[d + 0]; v.y *= a[d + 1]; v.z *= a[d + 2]; v.w *= a[d + 3];
        T[r][d + 0] = v.x; T[r][d + 1] = v.y;
        T[r][d + 2] = v.z; T[r][d + 3] = v.w;
        s += v.x + v.y + v.z;          // skip v.w: d%4==3 -> abs route
    }
    s += __shfl_down_sync(0xffffffffu, s, 4);
    s += __shfl_down_sync(0xffffffffu, s, 2);
    s += __shfl_down_sync(0xffffffffu, s, 1);
    if (seg == 0) sums[rowbase + r] = K_ABS * s;
    __syncthreads();

    #pragma unroll
    for (int k = 0; k < 4; k++) {
        int o  = t + k * 256;
        int d  = o >> 3;
        int rg = o & 7;
        float4 v;
        v.x = T[rg * 4 + 0][d];
        v.y = T[rg * 4 + 1][d];
        v.z = T[rg * 4 + 2][d];
        v.w = T[rg * 4 + 3][d];
        *(float4*)&dstT[d * NB + rowbase + rg * 4] = v;
    }
}

// ---------------------------------------------------------------------------
// Main: 32x32 tile, 64 threads, 4x4 micro-tile, cp.async double buffer.
// Small blocks -> ~14 blocks/SM -> 4096 blocks over ~2072 slots = 98.8%
// slot utilization (kills the 2-wave tail of the 64x64 version).
//   d%4 != 3 : acc += min(u,v)   (FMNMX alu + FADD fma)
//   d%4 == 3 : acc += |u-v|      (FADD + FADD|.|, fma pipe)
// out = ex2(P + Q + K_MIN*minsum + K_ABS*abssum)
// ---------------------------------------------------------------------------
__global__ __launch_bounds__(64, 14) void alcove_main(float* __restrict__ out)
{
    __shared__ float Xs[2][KCH * TILE];   // 2 x 4KB
    __shared__ float Es[2][KCH * TILE];   // 2 x 4KB

    int tid = threadIdx.x;        // 0..63
    int tx  = tid & 7;            // 8 col groups x 4 = 32 cols
    int ty  = tid >> 3;           // 8 row groups x 4 = 32 rows
    int rb  = blockIdx.y * TILE;
    int cb  = blockIdx.x * TILE;

    float mac[4][4];
    float aac[4][4];
    #pragma unroll
    for (int i = 0; i < 4; i++)
        #pragma unroll
        for (int j = 0; j < 4; j++) { mac[i][j] = 0.0f; aac[i][j] = 0.0f; }

    const float4* gx = (const float4*)g_XT;
    const float4* ge = (const float4*)g_ET;

    unsigned sx0 = (unsigned)__cvta_generic_to_shared(&Xs[0][0]);
    unsigned se0 = (unsigned)__cvta_generic_to_shared(&Es[0][0]);

    // per stage: KCH*TILE floats = 256 float4 per matrix; 64 thr x 4 each.
    auto issue_stage = [&](int kb, int buf) {
        int base = kb * KCH;
        unsigned xb = sx0 + buf * (KCH * TILE * 4);
        unsigned eb = se0 + buf * (KCH * TILE * 4);
        #pragma unroll
        for (int k = 0; k < 4; k++) {
            int fi = tid + k * 64;        // 0..255
            int d  = fi >> 3;             // 0..31
            int q  = fi & 7;              // 0..7 float4 within row
            cp16(xb + fi * 16, &gx[(base + d) * (NB/4) + (rb>>2) + q]);
            cp16(eb + fi * 16, &ge[(base + d) * (NB/4) + (cb>>2) + q]);
        }
        cp_commit();
    };

    issue_stage(0, 0);

    #pragma unroll 1
    for (int kb = 0; kb < NCH; kb++) {
        int buf = kb & 1;
        cp_wait<0>();
        __syncthreads();
        if (kb + 1 < NCH)
            issue_stage(kb + 1, buf ^ 1);

        const float* Xb = &Xs[buf][ty * 4];
        const float* Eb = &Es[buf][tx * 4];
        #pragma unroll
        for (int d4 = 0; d4 < KCH; d4 += 4) {
            #pragma unroll
            for (int dd = 0; dd < 3; dd++) {
                float4 xv = *(const float4*)&Xb[(d4 + dd) * TILE];
                float4 ev = *(const float4*)&Eb[(d4 + dd) * TILE];
                float x[4] = {xv.x, xv.y, xv.z, xv.w};
                #pragma unroll
                for (int i = 0; i < 4; i++) {
                    mac[i][0] += fminf(x[i], ev.x);
                    mac[i][1] += fminf(x[i], ev.y);
                    mac[i][2] += fminf(x[i], ev.z);
                    mac[i][3] += fminf(x[i], ev.w);
                }
            }
            {
                float4 xv = *(const float4*)&Xb[(d4 + 3) * TILE];
                float4 ev = *(const float4*)&Eb[(d4 + 3) * TILE];
                float x[4] = {xv.x, xv.y, xv.z, xv.w};
                #pragma unroll
                for (int i = 0; i < 4; i++) {
                    aac[i][0] += fabsf(x[i] - ev.x);
                    aac[i][1] += fabsf(x[i] - ev.y);
                    aac[i][2] += fabsf(x[i] - ev.z);
                    aac[i][3] += fabsf(x[i] - ev.w);
                }
            }
        }
    }

    // Epilogue: out = ex2(p + q + K_MIN*min + K_ABS*abs)
    float q0 = g_Q[cb + tx * 4 + 0];
    float q1 = g_Q[cb + tx * 4 + 1];
    float q2 = g_Q[cb + tx * 4 + 2];
    float q3 = g_Q[cb + tx * 4 + 3];
    #pragma unroll
    for (int i = 0; i < 4; i++) {
        int r = rb + ty * 4 + i;
        float p = g_P[r];
        float4 o;
        o.x = ex2(fmaf(K_MIN, mac[i][0], fmaf(K_ABS, aac[i][0], p + q0)));
        o.y = ex2(fmaf(K_MIN, mac[i][1], fmaf(K_ABS, aac[i][1], p + q1)));
        o.z = ex2(fmaf(K_MIN, mac[i][2], fmaf(K_ABS, aac[i][2], p + q2)));
        o.w = ex2(fmaf(K_MIN, mac[i][3], fmaf(K_ABS, aac[i][3], p + q3)));
        *(float4*)&out[r * NB + cb + tx * 4] = o;
    }
}

// ---------------------------------------------------------------------------
extern "C" void kernel_launch(void* const* d_in, const int* in_sizes, int n_in,
                              void* d_out, int out_size)
{
    const float* inputs    = (const float*)d_in[0];
    const float* exemplars = (const float*)d_in[1];
    const float* attn      = (const float*)d_in[2];
    float* out = (float*)d_out;

    prep2_kernel<<<128, 256>>>(inputs, exemplars, attn);

    dim3 grid(NB / TILE, NB / TILE);   // 64 x 64 = 4096 tiles
    alcove_main<<<grid, 64>>>(out);
}

// round 14
// speedup vs baseline: 1.0831x; 1.0831x over previous
#include <cuda_runtime.h>

#define NB   2048
#define ND   128
#define TILE 64          // output tile edge
#define KCH  32          // dims per pipeline stage
#define NCH  (ND / KCH)

// exponent constants, pre-scaled by log2(e) for ex2.approx
#define K_MIN  18.755035531556525f    //  13.0 * log2(e)
#define K_ABS  -9.3775177657782625f   //  -6.5 * log2(e)

// Scratch
__device__ float g_XT[ND * NB];   // attn-scaled (x0.5 on d%4==3), transposed
__device__ float g_ET[ND * NB];
__device__ float g_P[NB];         // K_ABS * sum over d%4!=3 of attn*x
__device__ float g_Q[NB];

__device__ __forceinline__ void cp16(unsigned smem_addr, const void* gptr) {
    asm volatile("cp.async.ca.shared.global [%0], [%1], 16;\n"
                 :: "r"(smem_addr), "l"(gptr));
}
__device__ __forceinline__ void cp_commit() {
    asm volatile("cp.async.commit_group;\n");
}
template<int N>
__device__ __forceinline__ void cp_wait() {
    asm volatile("cp.async.wait_group %0;\n" :: "n"(N));
}
__device__ __forceinline__ float ex2(float x) {
    float r; asm("ex2.approx.f32 %0, %1;" : "=f"(r) : "f"(x)); return r;
}

// ---------------------------------------------------------------------------
// Prep: transpose + attn-scale + partial rowsum (d%4 != 3), log2e-scaled.
// d%4==3 dims additionally scaled by 0.5 so the main kernel can fold the
// abs-route into the SAME accumulator as the min-route (13*(min) - 13*0.5|.|).
// ---------------------------------------------------------------------------
__global__ __launch_bounds__(256) void prep2_kernel(
    const float* __restrict__ X, const float* __restrict__ E,
    const float* __restrict__ attn)
{
    __shared__ float a[ND];
    __shared__ float T[32][ND + 1];

    int bid = blockIdx.x;
    bool isE = bid >= 64;
    const float* src = isE ? E : X;
    float* dstT      = isE ? g_ET : g_XT;
    float* sums      = isE ? g_Q  : g_P;
    int rowbase = (bid & 63) * 32;

    int t = threadIdx.x;
    if (t < ND) a[t] = attn[t] * ((t & 3) == 3 ? 0.5f : 1.0f);
    __syncthreads();

    int r   = t >> 3;
    int seg = t & 7;
    const float4* srow = (const float4*)&src[(rowbase + r) * ND + seg * 16];
    float s = 0.0f;
    #pragma unroll
    for (int k = 0; k < 4; k++) {
        float4 v = srow[k];
        int d = seg * 16 + k * 4;
        v.x *= a[d + 0]; v.y *= a[d + 1]; v.z *= a[d + 2]; v.w *= a[d + 3];
        T[r][d + 0] = v.x; T[r][d + 1] = v.y;
        T[r][d + 2] = v.z; T[r][d + 3] = v.w;
        s += v.x + v.y + v.z;          // skip v.w: d%4==3 -> abs route
    }
    s += __shfl_down_sync(0xffffffffu, s, 4);
    s += __shfl_down_sync(0xffffffffu, s, 2);
    s += __shfl_down_sync(0xffffffffu, s, 1);
    if (seg == 0) sums[rowbase + r] = K_ABS * s;
    __syncthreads();

    #pragma unroll
    for (int k = 0; k < 4; k++) {
        int o  = t + k * 256;
        int d  = o >> 3;
        int rg = o & 7;
        float4 v;
        v.x = T[rg * 4 + 0][d];
        v.y = T[rg * 4 + 1][d];
        v.z = T[rg * 4 + 2][d];
        v.w = T[rg * 4 + 3][d];
        *(float4*)&dstT[d * NB + rowbase + rg * 4] = v;
    }
}

// ---------------------------------------------------------------------------
// Main: 64x64 tile, 256 threads, 4x4 micro-tile, cp.async double buffer,
// SINGLE merged accumulator:
//   d%4 != 3 : acc += min(u,v)      (FMNMX alu + FADD fma)
//   d%4 == 3 : acc -= |u' - v'|     (FADD + FADD.neg-abs, fma pipe)
// out = ex2(P + Q + K_MIN*acc)
// ---------------------------------------------------------------------------
__global__ __launch_bounds__(256, 5) void alcove_main(float* __restrict__ out)
{
    __shared__ float Xs[2][KCH * TILE];   // 2 x 8KB
    __shared__ float Es[2][KCH * TILE];   // 2 x 8KB

    int tid = threadIdx.x;
    int tx  = tid & 15;
    int ty  = tid >> 4;
    int rb  = blockIdx.y * TILE;
    int cb  = blockIdx.x * TILE;

    float acc[4][4];
    #pragma unroll
    for (int i = 0; i < 4; i++)
        #pragma unroll
        for (int j = 0; j < 4; j++) acc[i][j] = 0.0f;

    int fi0 = tid, fi1 = tid + 256;
    int d0 = fi0 >> 4, q0i = fi0 & 15;
    int d1 = fi1 >> 4, q1i = fi1 & 15;

    const float4* gx = (const float4*)g_XT;
    const float4* ge = (const float4*)g_ET;

    unsigned sx0 = (unsigned)__cvta_generic_to_shared(&Xs[0][0]);
    unsigned se0 = (unsigned)__cvta_generic_to_shared(&Es[0][0]);

    auto issue_stage = [&](int kb, int buf) {
        int base = kb * KCH;
        unsigned xb = sx0 + buf * (KCH * TILE * 4);
        unsigned eb = se0 + buf * (KCH * TILE * 4);
        cp16(xb + (d0 * 16 + q0i) * 16, &gx[(base + d0) * (NB/4) + (rb>>2) + q0i]);
        cp16(xb + (d1 * 16 + q1i) * 16, &gx[(base + d1) * (NB/4) + (rb>>2) + q1i]);
        cp16(eb + (d0 * 16 + q0i) * 16, &ge[(base + d0) * (NB/4) + (cb>>2) + q0i]);
        cp16(eb + (d1 * 16 + q1i) * 16, &ge[(base + d1) * (NB/4) + (cb>>2) + q1i]);
        cp_commit();
    };

    issue_stage(0, 0);

    #pragma unroll 1
    for (int kb = 0; kb < NCH; kb++) {
        int buf = kb & 1;
        cp_wait<0>();          // stage kb data landed
        __syncthreads();       // also: everyone finished reading buf^1
        if (kb + 1 < NCH)
            issue_stage(kb + 1, buf ^ 1);

        const float* Xb = &Xs[buf][ty * 4];
        const float* Eb = &Es[buf][tx * 4];
        #pragma unroll
        for (int d4 = 0; d4 < KCH; d4 += 4) {
            #pragma unroll
            for (int dd = 0; dd < 3; dd++) {
                float4 xv = *(const float4*)&Xb[(d4 + dd) * TILE];
                float4 ev = *(const float4*)&Eb[(d4 + dd) * TILE];
                float x[4] = {xv.x, xv.y, xv.z, xv.w};
                #pragma unroll
                for (int i = 0; i < 4; i++) {
                    acc[i][0] += fminf(x[i], ev.x);
                    acc[i][1] += fminf(x[i], ev.y);
                    acc[i][2] += fminf(x[i], ev.z);
                    acc[i][3] += fminf(x[i], ev.w);
                }
            }
            {
                float4 xv = *(const float4*)&Xb[(d4 + 3) * TILE];
                float4 ev = *(const float4*)&Eb[(d4 + 3) * TILE];
                float x[4] = {xv.x, xv.y, xv.z, xv.w};
                #pragma unroll
                for (int i = 0; i < 4; i++) {
                    acc[i][0] -= fabsf(x[i] - ev.x);
                    acc[i][1] -= fabsf(x[i] - ev.y);
                    acc[i][2] -= fabsf(x[i] - ev.z);
                    acc[i][3] -= fabsf(x[i] - ev.w);
                }
            }
        }
    }

    // Epilogue: out = ex2(p + q + K_MIN*acc)
    float q0 = g_Q[cb + tx * 4 + 0];
    float q1 = g_Q[cb + tx * 4 + 1];
    float q2 = g_Q[cb + tx * 4 + 2];
    float q3 = g_Q[cb + tx * 4 + 3];
    #pragma unroll
    for (int i = 0; i < 4; i++) {
        int r = rb + ty * 4 + i;
        float p = g_P[r];
        float4 o;
        o.x = ex2(fmaf(K_MIN, acc[i][0], p + q0));
        o.y = ex2(fmaf(K_MIN, acc[i][1], p + q1));
        o.z = ex2(fmaf(K_MIN, acc[i][2], p + q2));
        o.w = ex2(fmaf(K_MIN, acc[i][3], p + q3));
        *(float4*)&out[r * NB + cb + tx * 4] = o;
    }
}

// ---------------------------------------------------------------------------
extern "C" void kernel_launch(void* const* d_in, const int* in_sizes, int n_in,
                              void* d_out, int out_size)
{
    const float* inputs    = (const float*)d_in[0];
    const float* exemplars = (const float*)d_in[1];
    const float* attn      = (const float*)d_in[2];
    float* out = (float*)d_out;

    prep2_kernel<<<128, 256>>>(inputs, exemplars, attn);

    dim3 grid(NB / TILE, NB / TILE);   // 32 x 32 = 1024 tiles
    alcove_main<<<grid, 256>>>(out);
}